// round 2
// baseline (speedup 1.0000x reference)
#include <cuda_runtime.h>
#include <math.h>

#define BB 64
#define TT 1024
#define DD 128
#define QT 32
#define KT 64
#define DPAD 132              // 128 + 4 pad: breaks smem bank conflicts
#define NTHREADS 256
#define MASK_FILL_F (-4294967295.0f)   // float(-2^32 + 1)
#define SCALE 0.08838834764831845f     // 1/sqrt(128)

// 0 = uint8, 1 = int32, 2 = float32 storage for the boolean mask
__device__ int g_mask_mode;

__global__ void probe_mask_kernel(const unsigned char* __restrict__ mask)
{
    if (threadIdx.x != 0 || blockIdx.x != 0) return;

    // float32 storage <=> first 1024 words are all exactly 0.0f or 1.0f.
    // (u8 storage packs random 0/1 bytes -> words are denormal soup;
    //  i32 storage gives 0 or 1.4e-45, never 1.0f.)
    const float* mf = (const float*)mask;
    bool all_f01 = true;
    for (int i = 0; i < 1024; ++i) {
        float f = mf[i];
        if (f != 0.0f && f != 1.0f) { all_f01 = false; break; }
    }
    if (all_f01) { g_mask_mode = 2; return; }

    // uint8 storage <=> nonzero bytes appear at offsets %4 != 0
    // (int32 {0,1} little-endian keeps those byte lanes all-zero).
    int any_high = 0;
    for (int i = 0; i < 4096; i += 4)
        any_high |= (mask[i + 1] | mask[i + 2] | mask[i + 3]);
    g_mask_mode = any_high ? 0 : 1;
}

__device__ __forceinline__ bool mask_at(const void* __restrict__ m, size_t idx, int mode)
{
    if (mode == 0) return ((const unsigned char*)m)[idx] != 0;
    if (mode == 1) return ((const int*)m)[idx] != 0;
    return ((const float*)m)[idx] != 0.0f;
}

__global__ __launch_bounds__(NTHREADS, 1)
void mh_attn_fused_kernel(const float* __restrict__ key,
                          const float* __restrict__ value,
                          const float* __restrict__ query,
                          const void* __restrict__ mask,
                          const float* __restrict__ qmask,
                          float* __restrict__ out_res,
                          float* __restrict__ out_attn)
{
    extern __shared__ float smem[];
    float* sS  = smem;                      // QT * TT   (32 x 1024 scores)
    float* sQ  = sS + QT * TT;              // QT * DPAD
    float* sKV = sQ + QT * DPAD;            // KT * DPAD (K tile, then V tile)

    const int b   = blockIdx.x >> 5;        // 64 batches
    const int q0  = (blockIdx.x & 31) * QT; // 32 q-tiles per batch
    const int tid = threadIdx.x;
    const int tx  = tid & 15;               // 16 k/d groups
    const int ty  = tid >> 4;               // 16 q groups
    const int qr0 = ty * 2;
    const int qr1 = qr0 + 1;
    const int mmode = g_mask_mode;

    // ---- load Q tile: 32 x 128 ----
    const float4* Qg = reinterpret_cast<const float4*>(query + ((size_t)b * TT + q0) * DD);
    for (int i = tid; i < QT * DD / 4; i += NTHREADS) {
        int row = i >> 5, c4 = i & 31;   // 32 float4 per row
        *reinterpret_cast<float4*>(sQ + row * DPAD + c4 * 4) = Qg[i];
    }

    // ---- Phase 1: S = scale * Q K^T, masked, into sS ----
    const size_t mbase = (size_t)b * TT * TT;
    for (int kt = 0; kt < TT / KT; ++kt) {
        const int k0 = kt * KT;
        const float4* Kg = reinterpret_cast<const float4*>(key + ((size_t)b * TT + k0) * DD);
        __syncthreads();  // previous sKV consumers done (and Q visible on iter 0)
        for (int i = tid; i < KT * DD / 4; i += NTHREADS) {
            int row = i >> 5, c4 = i & 31;
            *reinterpret_cast<float4*>(sKV + row * DPAD + c4 * 4) = Kg[i];
        }
        __syncthreads();

        float acc0[4] = {0.f, 0.f, 0.f, 0.f};
        float acc1[4] = {0.f, 0.f, 0.f, 0.f};
        #pragma unroll 4
        for (int d = 0; d < DD; d += 4) {
            float4 qa = *reinterpret_cast<const float4*>(sQ + qr0 * DPAD + d);
            float4 qb = *reinterpret_cast<const float4*>(sQ + qr1 * DPAD + d);
            #pragma unroll
            for (int j = 0; j < 4; ++j) {
                float4 kv = *reinterpret_cast<const float4*>(sKV + (tx + 16 * j) * DPAD + d);
                acc0[j] = fmaf(qa.x, kv.x, acc0[j]);
                acc0[j] = fmaf(qa.y, kv.y, acc0[j]);
                acc0[j] = fmaf(qa.z, kv.z, acc0[j]);
                acc0[j] = fmaf(qa.w, kv.w, acc0[j]);
                acc1[j] = fmaf(qb.x, kv.x, acc1[j]);
                acc1[j] = fmaf(qb.y, kv.y, acc1[j]);
                acc1[j] = fmaf(qb.z, kv.z, acc1[j]);
                acc1[j] = fmaf(qb.w, kv.w, acc1[j]);
            }
        }
        #pragma unroll
        for (int j = 0; j < 4; ++j) {
            int k = k0 + tx + 16 * j;
            float s0 = acc0[j] * SCALE;
            float s1 = acc1[j] * SCALE;
            if (mask_at(mask, mbase + (size_t)(q0 + qr0) * TT + k, mmode)) s0 = MASK_FILL_F;
            if (mask_at(mask, mbase + (size_t)(q0 + qr1) * TT + k, mmode)) s1 = MASK_FILL_F;
            sS[qr0 * TT + k] = s0;
            sS[qr1 * TT + k] = s1;
        }
    }
    __syncthreads();

    // ---- Phase 2: row softmax (warp per row), * query_mask, stream attn out ----
    {
        const int warp = tid >> 5, lane = tid & 31;
        float* attn_g = out_attn + ((size_t)b * TT + q0) * TT;
        for (int r = warp; r < QT; r += 8) {
            float* row = sS + r * TT;
            float mx = -3.402823466e38f;
            for (int i = lane; i < TT; i += 32) mx = fmaxf(mx, row[i]);
            #pragma unroll
            for (int o = 16; o; o >>= 1) mx = fmaxf(mx, __shfl_xor_sync(0xffffffffu, mx, o));
            float sum = 0.f;
            for (int i = lane; i < TT; i += 32) {
                float e = __expf(row[i] - mx);
                sum += e;
                row[i] = e;
            }
            #pragma unroll
            for (int o = 16; o; o >>= 1) sum += __shfl_xor_sync(0xffffffffu, sum, o);
            float inv = qmask[(size_t)b * TT + q0 + r] / sum;
            for (int i = lane; i < TT; i += 32) {
                float v = row[i] * inv;
                row[i] = v;
                attn_g[(size_t)r * TT + i] = v;
            }
        }
    }
    __syncthreads();

    // ---- Phase 3: result = P @ V ----
    float racc0[8] = {0.f, 0.f, 0.f, 0.f, 0.f, 0.f, 0.f, 0.f};
    float racc1[8] = {0.f, 0.f, 0.f, 0.f, 0.f, 0.f, 0.f, 0.f};
    for (int kt = 0; kt < TT / KT; ++kt) {
        const float4* Vg = reinterpret_cast<const float4*>(value + ((size_t)b * TT + kt * KT) * DD);
        __syncthreads();
        for (int i = tid; i < KT * DD / 4; i += NTHREADS) {
            int row = i >> 5, c4 = i & 31;
            *reinterpret_cast<float4*>(sKV + row * DPAD + c4 * 4) = Vg[i];
        }
        __syncthreads();

        const float* p0r = sS + qr0 * TT + kt * KT;
        const float* p1r = sS + qr1 * TT + kt * KT;
        #pragma unroll 4
        for (int kk = 0; kk < KT; ++kk) {
            float p0 = p0r[kk];
            float p1 = p1r[kk];
            const float* vr = sKV + kk * DPAD + tx * 2;
            #pragma unroll
            for (int m = 0; m < 4; ++m) {
                float2 v = *reinterpret_cast<const float2*>(vr + 32 * m);
                racc0[2 * m]     = fmaf(p0, v.x, racc0[2 * m]);
                racc0[2 * m + 1] = fmaf(p0, v.y, racc0[2 * m + 1]);
                racc1[2 * m]     = fmaf(p1, v.x, racc1[2 * m]);
                racc1[2 * m + 1] = fmaf(p1, v.y, racc1[2 * m + 1]);
            }
        }
    }

    float* o0 = out_res + ((size_t)b * TT + q0 + qr0) * DD + tx * 2;
    float* o1 = out_res + ((size_t)b * TT + q0 + qr1) * DD + tx * 2;
    #pragma unroll
    for (int m = 0; m < 4; ++m) {
        *reinterpret_cast<float2*>(o0 + 32 * m) = make_float2(racc0[2 * m], racc0[2 * m + 1]);
        *reinterpret_cast<float2*>(o1 + 32 * m) = make_float2(racc1[2 * m], racc1[2 * m + 1]);
    }
}

extern "C" void kernel_launch(void* const* d_in, const int* in_sizes, int n_in,
                              void* d_out, int out_size) {
    const float* key           = (const float*)d_in[0];
    const float* value         = (const float*)d_in[1];
    const float* query         = (const float*)d_in[2];
    const void*  mask          = d_in[3];
    const float* qmask         = (const float*)d_in[4];
    // d_in[5] = num_hidden (128), folded into SCALE constant.

    float* out      = (float*)d_out;
    float* out_res  = out;                          // [B, T, D] first (tuple order)
    float* out_attn = out + (size_t)BB * TT * DD;   // [B, T, T] second

    probe_mask_kernel<<<1, 32>>>((const unsigned char*)mask);

    const size_t smem_bytes = (size_t)(QT * TT + QT * DPAD + KT * DPAD) * sizeof(float);
    cudaFuncSetAttribute(mh_attn_fused_kernel,
                         cudaFuncAttributeMaxDynamicSharedMemorySize, (int)smem_bytes);

    dim3 grid(BB * (TT / QT));   // 2048 CTAs
    mh_attn_fused_kernel<<<grid, NTHREADS, smem_bytes>>>(
        key, value, query, mask, qmask, out_res, out_attn);
}

// round 3
// speedup vs baseline: 1.6754x; 1.6754x over previous
#include <cuda_runtime.h>
#include <cuda_bf16.h>

#define BB 64
#define TT 1024
#define DD 128
#define QT 32
#define KTILE 128
#define NTHREADS 256
#define SSTRIDE 1032           // f32 stride of score rows (pad kills STS conflicts)
#define TSTRIDE 69             // u32 stride of bf16 tile rows (bank = 5g+t, conflict-free)
#define MASK_FILL_F (-4294967295.0f)
#define SCALE 0.08838834764831845f

typedef unsigned int u32;

// ---------------- mask dtype probe (u8 / i32 / f32) ----------------
__device__ int g_mask_mode;

__global__ void probe_mask_kernel(const unsigned char* __restrict__ mask)
{
    if (threadIdx.x != 0 || blockIdx.x != 0) return;
    const float* mf = (const float*)mask;
    bool all_f01 = true;
    for (int i = 0; i < 1024; ++i) {
        float f = mf[i];
        if (f != 0.0f && f != 1.0f) { all_f01 = false; break; }
    }
    if (all_f01) { g_mask_mode = 2; return; }
    int any_high = 0;
    for (int i = 0; i < 4096; i += 4)
        any_high |= (mask[i + 1] | mask[i + 2] | mask[i + 3]);
    g_mask_mode = any_high ? 0 : 1;
}

__device__ __forceinline__ bool mask_at(const void* __restrict__ m, size_t idx, int mode)
{
    if (mode == 0) return ((const unsigned char*)m)[idx] != 0;
    if (mode == 1) return ((const int*)m)[idx] != 0;
    return ((const float*)m)[idx] != 0.0f;
}

// ---------------- helpers ----------------
__device__ __forceinline__ void cvt_split2(float x0, float x1, u32& hi, u32& lo)
{
    __nv_bfloat16 h0 = __float2bfloat16(x0);
    __nv_bfloat16 h1 = __float2bfloat16(x1);
    __nv_bfloat16 l0 = __float2bfloat16(x0 - __bfloat162float(h0));
    __nv_bfloat16 l1 = __float2bfloat16(x1 - __bfloat162float(h1));
    __nv_bfloat162 H(h0, h1);   // .x = low 16 bits = even element
    __nv_bfloat162 L(l0, l1);
    hi = *reinterpret_cast<u32*>(&H);
    lo = *reinterpret_cast<u32*>(&L);
}

__device__ __forceinline__ void mma16816(float* c, const u32* a, const u32* b)
{
    asm volatile(
        "mma.sync.aligned.m16n8k16.row.col.f32.bf16.bf16.f32 "
        "{%0,%1,%2,%3}, {%4,%5,%6,%7}, {%8,%9}, {%0,%1,%2,%3};"
        : "+f"(c[0]), "+f"(c[1]), "+f"(c[2]), "+f"(c[3])
        : "r"(a[0]), "r"(a[1]), "r"(a[2]), "r"(a[3]), "r"(b[0]), "r"(b[1]));
}

// ---------------- fused attention kernel ----------------
__global__ __launch_bounds__(NTHREADS, 1)
void mh_attn_mma_kernel(const float* __restrict__ key,
                        const float* __restrict__ value,
                        const float* __restrict__ query,
                        const void* __restrict__ mask,
                        const float* __restrict__ qmask,
                        float* __restrict__ out_res,
                        float* __restrict__ out_attn)
{
    extern __shared__ char smem_raw[];
    float* sS    = (float*)smem_raw;                     // 32 x 1032 f32   (132096 B)
    u32*   sKVhi = (u32*)(smem_raw + 132096);            // 128 x 69 u32    (35328 B)
    u32*   sKVlo = sKVhi + 128 * TSTRIDE;                // 128 x 69 u32    (35328 B)
    u32*   sQPhi = sKVlo + 128 * TSTRIDE;                // 32 x 69 u32     (8832 B)
    u32*   sQPlo = sQPhi + 32 * TSTRIDE;                 // 32 x 69 u32     (8832 B)

    const int b    = blockIdx.x >> 5;
    const int q0   = (blockIdx.x & 31) * QT;
    const int tid  = threadIdx.x;
    const int warp = tid >> 5;
    const int lane = tid & 31;
    const int g    = lane >> 2;     // 0..7
    const int t    = lane & 3;      // 0..3
    const int n0   = warp * 16;     // per-warp 16-wide column slice

    // ---- convert Q tile (pre-scaled) into sQP hi/lo ----
    {
        const float2* Qg = (const float2*)(query + ((size_t)b * TT + q0) * DD);
        #pragma unroll
        for (int j = tid; j < QT * DD / 2; j += NTHREADS) {
            int r = j >> 6, c2 = j & 63;
            float2 v = Qg[j];
            u32 hi, lo;
            cvt_split2(v.x * SCALE, v.y * SCALE, hi, lo);
            sQPhi[r * TSTRIDE + c2] = hi;
            sQPlo[r * TSTRIDE + c2] = lo;
        }
    }

    // =========== Phase 1: S = (Q*scale) @ K^T ===========
    for (int kt = 0; kt < TT / KTILE; ++kt) {
        __syncthreads();   // protect sKV from previous iteration's consumers
        const float2* Kg = (const float2*)(key + ((size_t)b * TT + kt * KTILE) * DD);
        #pragma unroll
        for (int j = tid; j < KTILE * DD / 2; j += NTHREADS) {
            int r = j >> 6, c2 = j & 63;
            float2 v = Kg[j];
            u32 hi, lo;
            cvt_split2(v.x, v.y, hi, lo);
            sKVhi[r * TSTRIDE + c2] = hi;
            sKVlo[r * TSTRIDE + c2] = lo;
        }
        __syncthreads();

        float acc[2][2][4];
        #pragma unroll
        for (int mt = 0; mt < 2; ++mt)
            #pragma unroll
            for (int nt = 0; nt < 2; ++nt)
                #pragma unroll
                for (int i = 0; i < 4; ++i) acc[mt][nt][i] = 0.f;

        #pragma unroll
        for (int ks = 0; ks < 8; ++ks) {
            const int base = ks * 8 + t;
            u32 ahi[2][4], alo[2][4], bhi[2][2], blo[2][2];
            #pragma unroll
            for (int mt = 0; mt < 2; ++mt) {
                int r = mt * 16 + g;
                ahi[mt][0] = sQPhi[r * TSTRIDE + base];
                ahi[mt][1] = sQPhi[(r + 8) * TSTRIDE + base];
                ahi[mt][2] = sQPhi[r * TSTRIDE + base + 4];
                ahi[mt][3] = sQPhi[(r + 8) * TSTRIDE + base + 4];
                alo[mt][0] = sQPlo[r * TSTRIDE + base];
                alo[mt][1] = sQPlo[(r + 8) * TSTRIDE + base];
                alo[mt][2] = sQPlo[r * TSTRIDE + base + 4];
                alo[mt][3] = sQPlo[(r + 8) * TSTRIDE + base + 4];
            }
            #pragma unroll
            for (int nt = 0; nt < 2; ++nt) {
                int rn = n0 + nt * 8 + g;
                bhi[nt][0] = sKVhi[rn * TSTRIDE + base];
                bhi[nt][1] = sKVhi[rn * TSTRIDE + base + 4];
                blo[nt][0] = sKVlo[rn * TSTRIDE + base];
                blo[nt][1] = sKVlo[rn * TSTRIDE + base + 4];
            }
            #pragma unroll
            for (int mt = 0; mt < 2; ++mt)
                #pragma unroll
                for (int nt = 0; nt < 2; ++nt) {
                    mma16816(acc[mt][nt], ahi[mt], bhi[nt]);
                    mma16816(acc[mt][nt], ahi[mt], blo[nt]);
                    mma16816(acc[mt][nt], alo[mt], bhi[nt]);
                }
        }

        // epilogue: raw scores -> sS (scale folded into Q)
        #pragma unroll
        for (int mt = 0; mt < 2; ++mt)
            #pragma unroll
            for (int nt = 0; nt < 2; ++nt) {
                int col = kt * KTILE + n0 + nt * 8 + 2 * t;
                int r = mt * 16 + g;
                *(float2*)&sS[r * SSTRIDE + col]       = make_float2(acc[mt][nt][0], acc[mt][nt][1]);
                *(float2*)&sS[(r + 8) * SSTRIDE + col] = make_float2(acc[mt][nt][2], acc[mt][nt][3]);
            }
    }
    __syncthreads();

    // =========== Phase 2: mask + softmax + query_mask, stream attn ===========
    {
        const int mmode = g_mask_mode;
        float* attn_g = out_attn + ((size_t)b * TT + q0) * TT;
        for (int r = warp; r < QT; r += 8) {
            float* row = sS + r * SSTRIDE;
            const size_t mrow = (size_t)b * TT * TT + (size_t)(q0 + r) * TT;
            float mx = -3.402823466e38f;
            for (int i = lane; i < TT; i += 32) {
                float s = row[i];
                if (mask_at(mask, mrow + i, mmode)) s = MASK_FILL_F;
                row[i] = s;
                mx = fmaxf(mx, s);
            }
            #pragma unroll
            for (int o = 16; o; o >>= 1) mx = fmaxf(mx, __shfl_xor_sync(0xffffffffu, mx, o));
            float sum = 0.f;
            for (int i = lane; i < TT; i += 32) {
                float e = __expf(row[i] - mx);
                sum += e;
                row[i] = e;
            }
            #pragma unroll
            for (int o = 16; o; o >>= 1) sum += __shfl_xor_sync(0xffffffffu, sum, o);
            float inv = qmask[(size_t)b * TT + q0 + r] / sum;
            for (int i = lane; i < TT; i += 32) {
                float v = row[i] * inv;
                row[i] = v;
                attn_g[(size_t)r * TT + i] = v;
            }
        }
    }

    // =========== Phase 3: result = P @ V ===========
    float racc[2][2][4];
    #pragma unroll
    for (int mt = 0; mt < 2; ++mt)
        #pragma unroll
        for (int nt = 0; nt < 2; ++nt)
            #pragma unroll
            for (int i = 0; i < 4; ++i) racc[mt][nt][i] = 0.f;

    for (int kt = 0; kt < TT / KTILE; ++kt) {
        __syncthreads();   // previous sKV/sQP consumers done (incl. phase-2 sS writes on kt=0)
        // V tile, transposed: sV[d][kseq-pair], packed as (v(2rp), v(2rp+1))
        const float* Vg = value + ((size_t)b * TT + kt * KTILE) * DD;
        #pragma unroll
        for (int j = tid; j < (KTILE / 2) * DD; j += NTHREADS) {
            int c = j & 127, rp = j >> 7;
            float v0 = Vg[(size_t)(2 * rp) * DD + c];
            float v1 = Vg[(size_t)(2 * rp + 1) * DD + c];
            u32 hi, lo;
            cvt_split2(v0, v1, hi, lo);
            sKVhi[c * TSTRIDE + rp] = hi;
            sKVlo[c * TSTRIDE + rp] = lo;
        }
        // P tile from sS
        #pragma unroll
        for (int j = tid; j < QT * KTILE / 2; j += NTHREADS) {
            int r = j >> 6, c2 = j & 63;
            float2 p = *(const float2*)&sS[r * SSTRIDE + kt * KTILE + 2 * c2];
            u32 hi, lo;
            cvt_split2(p.x, p.y, hi, lo);
            sQPhi[r * TSTRIDE + c2] = hi;
            sQPlo[r * TSTRIDE + c2] = lo;
        }
        __syncthreads();

        #pragma unroll
        for (int ks = 0; ks < 8; ++ks) {
            const int base = ks * 8 + t;
            u32 ahi[2][4], alo[2][4], bhi[2][2], blo[2][2];
            #pragma unroll
            for (int mt = 0; mt < 2; ++mt) {
                int r = mt * 16 + g;
                ahi[mt][0] = sQPhi[r * TSTRIDE + base];
                ahi[mt][1] = sQPhi[(r + 8) * TSTRIDE + base];
                ahi[mt][2] = sQPhi[r * TSTRIDE + base + 4];
                ahi[mt][3] = sQPhi[(r + 8) * TSTRIDE + base + 4];
                alo[mt][0] = sQPlo[r * TSTRIDE + base];
                alo[mt][1] = sQPlo[(r + 8) * TSTRIDE + base];
                alo[mt][2] = sQPlo[r * TSTRIDE + base + 4];
                alo[mt][3] = sQPlo[(r + 8) * TSTRIDE + base + 4];
            }
            #pragma unroll
            for (int nt = 0; nt < 2; ++nt) {
                int rn = n0 + nt * 8 + g;   // rn = d row of transposed V
                bhi[nt][0] = sKVhi[rn * TSTRIDE + base];
                bhi[nt][1] = sKVhi[rn * TSTRIDE + base + 4];
                blo[nt][0] = sKVlo[rn * TSTRIDE + base];
                blo[nt][1] = sKVlo[rn * TSTRIDE + base + 4];
            }
            #pragma unroll
            for (int mt = 0; mt < 2; ++mt)
                #pragma unroll
                for (int nt = 0; nt < 2; ++nt) {
                    mma16816(racc[mt][nt], ahi[mt], bhi[nt]);
                    mma16816(racc[mt][nt], ahi[mt], blo[nt]);
                    mma16816(racc[mt][nt], alo[mt], bhi[nt]);
                }
        }
    }

    // result epilogue
    #pragma unroll
    for (int mt = 0; mt < 2; ++mt)
        #pragma unroll
        for (int nt = 0; nt < 2; ++nt) {
            int d = n0 + nt * 8 + 2 * t;
            int q = q0 + mt * 16 + g;
            *(float2*)&out_res[((size_t)b * TT + q) * DD + d] =
                make_float2(racc[mt][nt][0], racc[mt][nt][1]);
            *(float2*)&out_res[((size_t)b * TT + q + 8) * DD + d] =
                make_float2(racc[mt][nt][2], racc[mt][nt][3]);
        }
}

extern "C" void kernel_launch(void* const* d_in, const int* in_sizes, int n_in,
                              void* d_out, int out_size) {
    const float* key   = (const float*)d_in[0];
    const float* value = (const float*)d_in[1];
    const float* query = (const float*)d_in[2];
    const void*  mask  = d_in[3];
    const float* qmask = (const float*)d_in[4];

    float* out      = (float*)d_out;
    float* out_res  = out;                          // [B, T, D] first (tuple order)
    float* out_attn = out + (size_t)BB * TT * DD;   // [B, T, T] second

    probe_mask_kernel<<<1, 32>>>((const unsigned char*)mask);

    const size_t smem_bytes = 132096 + 2 * (128 * TSTRIDE * 4) + 2 * (32 * TSTRIDE * 4);
    cudaFuncSetAttribute(mh_attn_mma_kernel,
                         cudaFuncAttributeMaxDynamicSharedMemorySize, (int)smem_bytes);

    dim3 grid(BB * (TT / QT));   // 2048 CTAs
    mh_attn_mma_kernel<<<grid, NTHREADS, smem_bytes>>>(
        key, value, query, mask, qmask, out_res, out_attn);
}

// round 5
// speedup vs baseline: 1.8677x; 1.1148x over previous
#include <cuda_runtime.h>
#include <cuda_bf16.h>

typedef unsigned int u32;

#define BB 64
#define TT 1024
#define DD 128
#define QT 32                  // q rows per CTA
#define KT 128                 // k-seq tile
#define NTHREADS 512
#define SSTRIDE 1032           // f32 stride of score rows
#define MASK_FILL_F (-4294967295.0f)
#define SCALE 0.08838834764831845f

// ---- smem layout (bytes): 256B-row bf16 tiles, 16B-unit XOR swizzle ----
#define SM_SS    0                         // 32 x 1032 f32 scores   (132096)
#define SM_KHI   132096                    // 128 x 128 bf16 (K / V) (32768)
#define SM_KLO   (SM_KHI + 32768)
#define SM_QPHI  (SM_KLO + 32768)          // 32 x 128 bf16 (Q / P)  (8192)
#define SM_QPLO  (SM_QPHI + 8192)
#define SM_TOTAL (SM_QPLO + 8192)          // 214016

// byte offset of 16B unit `unit` in row `row` (tile rows are 256B = 16 units)
#define SWZ_UNIT(row, unit) ((u32)(row) * 256u + (((u32)(unit) ^ ((u32)(row) & 7u)) << 4))
// byte offset for u32 col-pair c2 (c2 in [0,64))
#define SWZ_U32(row, c2) (SWZ_UNIT(row, (c2) >> 2) + (((u32)(c2) & 3u) << 2))

// ================= small helpers =================
__device__ __forceinline__ u32 smem_u32(const void* p) {
    u32 a;
    asm("{ .reg .u64 t; cvta.to.shared.u64 t, %1; cvt.u32.u64 %0, t; }" : "=r"(a) : "l"(p));
    return a;
}

__device__ __forceinline__ void ldm_x4(u32* r, u32 addr) {
    asm volatile("ldmatrix.sync.aligned.m8n8.x4.shared.b16 {%0,%1,%2,%3}, [%4];"
                 : "=r"(r[0]), "=r"(r[1]), "=r"(r[2]), "=r"(r[3]) : "r"(addr));
}
__device__ __forceinline__ void ldm_x4t(u32* r, u32 addr) {
    asm volatile("ldmatrix.sync.aligned.m8n8.x4.trans.shared.b16 {%0,%1,%2,%3}, [%4];"
                 : "=r"(r[0]), "=r"(r[1]), "=r"(r[2]), "=r"(r[3]) : "r"(addr));
}

__device__ __forceinline__ void mma16816(float* c, const u32* a, const u32* b)
{
    asm volatile(
        "mma.sync.aligned.m16n8k16.row.col.f32.bf16.bf16.f32 "
        "{%0,%1,%2,%3}, {%4,%5,%6,%7}, {%8,%9}, {%0,%1,%2,%3};"
        : "+f"(c[0]), "+f"(c[1]), "+f"(c[2]), "+f"(c[3])
        : "r"(a[0]), "r"(a[1]), "r"(a[2]), "r"(a[3]), "r"(b[0]), "r"(b[1]));
}

__device__ __forceinline__ void cvt_split2(float x0, float x1, u32& hi, u32& lo)
{
    __nv_bfloat16 h0 = __float2bfloat16(x0);
    __nv_bfloat16 h1 = __float2bfloat16(x1);
    __nv_bfloat16 l0 = __float2bfloat16(x0 - __bfloat162float(h0));
    __nv_bfloat16 l1 = __float2bfloat16(x1 - __bfloat162float(h1));
    __nv_bfloat162 H(h0, h1), L(l0, l1);
    hi = *reinterpret_cast<u32*>(&H);
    lo = *reinterpret_cast<u32*>(&L);
}

// ---------------- mask dtype probe (u8 / i32 / f32) ----------------
__device__ int g_mask_mode;

__global__ void probe_mask_kernel(const unsigned char* __restrict__ mask)
{
    if (threadIdx.x != 0 || blockIdx.x != 0) return;
    const float* mf = (const float*)mask;
    bool all_f01 = true;
    for (int i = 0; i < 1024; ++i) {
        float f = mf[i];
        if (f != 0.0f && f != 1.0f) { all_f01 = false; break; }
    }
    if (all_f01) { g_mask_mode = 2; return; }
    int any_high = 0;
    for (int i = 0; i < 4096; i += 4)
        any_high |= (mask[i + 1] | mask[i + 2] | mask[i + 3]);
    g_mask_mode = any_high ? 0 : 1;
}

__device__ __forceinline__ bool mask_at(const void* __restrict__ m, size_t idx, int mode)
{
    if (mode == 0) return ((const unsigned char*)m)[idx] != 0;
    if (mode == 1) return ((const int*)m)[idx] != 0;
    return ((const float*)m)[idx] != 0.0f;
}

// ================= fused attention =================
__global__ __launch_bounds__(NTHREADS, 1)
void mh_attn_mma2_kernel(const float* __restrict__ key,
                         const float* __restrict__ value,
                         const float* __restrict__ query,
                         const void* __restrict__ mask,
                         const float* __restrict__ qmask,
                         float* __restrict__ out_res,
                         float* __restrict__ out_attn)
{
    extern __shared__ char smem[];
    float* sS = (float*)smem;
    const u32 sb = smem_u32(smem);

    const int b    = blockIdx.x >> 5;
    const int q0   = (blockIdx.x & 31) * QT;
    const int tid  = threadIdx.x;
    const int wid  = tid >> 5;
    const int lane = tid & 31;
    const int grp  = lane >> 3;     // ldmatrix address group 0..3
    const int sub  = lane & 7;
    const int g    = lane >> 2;     // mma row group 0..7
    const int t    = lane & 3;
    const int wm   = wid & 1;       // 2 m-slices of 16 rows
    const int wn   = wid >> 1;      // 8 n-slices of 16 cols
    const int m0   = wm * 16;
    const int n0   = wn * 16;

    // ---- convert Q (scaled) into QP tile ----
    for (int j = tid; j < QT * 64; j += NTHREADS) {
        int r = j >> 6, c2 = j & 63;
        float2 q2 = *(const float2*)(query + ((size_t)b * TT + q0 + r) * DD + 2 * c2);
        u32 hi, lo;
        cvt_split2(q2.x * SCALE, q2.y * SCALE, hi, lo);
        u32 off = SWZ_U32(r, c2);
        *(u32*)(smem + SM_QPHI + off) = hi;
        *(u32*)(smem + SM_QPLO + off) = lo;
    }
    __syncthreads();

    // ---- cache Q fragments in registers (m16 x k128, hi+lo) ----
    u32 qhi[8][4], qlo[8][4];
    {
        int rowA = m0 + sub + ((grp & 1) << 3);
        #pragma unroll
        for (int ks = 0; ks < 8; ++ks) {
            int unit = 2 * ks + (grp >> 1);
            u32 off = SWZ_UNIT(rowA, unit);
            ldm_x4(qhi[ks], sb + SM_QPHI + off);
            ldm_x4(qlo[ks], sb + SM_QPLO + off);
        }
    }

    // =========== Phase 1: S = (Q*scale) @ K^T -> sS ===========
    for (int kt = 0; kt < TT / KT; ++kt) {
        __syncthreads();   // all warps done reading previous K tile
        for (int j = tid; j < KT * 64; j += NTHREADS) {
            int r = j >> 6, c2 = j & 63;
            float2 k2 = *(const float2*)(key + ((size_t)b * TT + kt * KT + r) * DD + 2 * c2);
            u32 hi, lo;
            cvt_split2(k2.x, k2.y, hi, lo);
            u32 off = SWZ_U32(r, c2);
            *(u32*)(smem + SM_KHI + off) = hi;
            *(u32*)(smem + SM_KLO + off) = lo;
        }
        __syncthreads();

        float acc[2][4] = {{0.f,0.f,0.f,0.f},{0.f,0.f,0.f,0.f}};
        const int rowB = n0 + sub + ((grp >> 1) << 3);
        #pragma unroll
        for (int ks = 0; ks < 8; ++ks) {
            int unit = 2 * ks + (grp & 1);
            u32 off = SWZ_UNIT(rowB, unit);
            u32 bh[4], bl[4];
            ldm_x4(bh, sb + SM_KHI + off);   // r0,r1 = tile n0; r2,r3 = tile n0+8
            ldm_x4(bl, sb + SM_KLO + off);
            #pragma unroll
            for (int tile = 0; tile < 2; ++tile) {
                mma16816(acc[tile], qhi[ks], bh + 2 * tile);
                mma16816(acc[tile], qhi[ks], bl + 2 * tile);
                mma16816(acc[tile], qlo[ks], bh + 2 * tile);
            }
        }
        #pragma unroll
        for (int tile = 0; tile < 2; ++tile) {
            int col = kt * KT + n0 + tile * 8 + 2 * t;
            int row = m0 + g;
            *(float2*)&sS[row * SSTRIDE + col]       = make_float2(acc[tile][0], acc[tile][1]);
            *(float2*)&sS[(row + 8) * SSTRIDE + col] = make_float2(acc[tile][2], acc[tile][3]);
        }
    }
    __syncthreads();

    // =========== Phase 2: mask + softmax + query_mask, stream attn ===========
    {
        const int mmode = g_mask_mode;
        float* attn_g = out_attn + ((size_t)b * TT + q0) * TT;
        for (int r = wid; r < QT; r += 16) {
            float* row = sS + r * SSTRIDE;
            const size_t mrow = (size_t)b * TT * TT + (size_t)(q0 + r) * TT;
            float mx = -3.402823466e38f;
            for (int i = lane; i < TT; i += 32) {
                float s = row[i];
                if (mask_at(mask, mrow + i, mmode)) s = MASK_FILL_F;
                row[i] = s;
                mx = fmaxf(mx, s);
            }
            #pragma unroll
            for (int o = 16; o; o >>= 1) mx = fmaxf(mx, __shfl_xor_sync(0xffffffffu, mx, o));
            float sum = 0.f;
            for (int i = lane; i < TT; i += 32) {
                float e = __expf(row[i] - mx);
                sum += e;
                row[i] = e;
            }
            #pragma unroll
            for (int o = 16; o; o >>= 1) sum += __shfl_xor_sync(0xffffffffu, sum, o);
            float inv = qmask[(size_t)b * TT + q0 + r] / sum;
            for (int i = lane; i < TT; i += 32) {
                float v = row[i] * inv;
                row[i] = v;
                attn_g[(size_t)r * TT + i] = v;
            }
        }
    }

    // =========== Phase 3: result = P @ V ===========
    float racc[2][4] = {{0.f,0.f,0.f,0.f},{0.f,0.f,0.f,0.f}};
    for (int kt = 0; kt < TT / KT; ++kt) {
        __syncthreads();   // previous V/P consumers done (and phase-2 sS final on kt=0)
        // V tile (row-major, k-seq rows x d cols) — no transpose needed (.trans ldmatrix)
        for (int j = tid; j < KT * 64; j += NTHREADS) {
            int r = j >> 6, c2 = j & 63;
            float2 v2 = *(const float2*)(value + ((size_t)b * TT + kt * KT + r) * DD + 2 * c2);
            u32 hi, lo;
            cvt_split2(v2.x, v2.y, hi, lo);
            u32 off = SWZ_U32(r, c2);
            *(u32*)(smem + SM_KHI + off) = hi;
            *(u32*)(smem + SM_KLO + off) = lo;
        }
        // P tile from sS
        for (int j = tid; j < QT * 64; j += NTHREADS) {
            int r = j >> 6, c2 = j & 63;
            float2 p2 = *(const float2*)&sS[r * SSTRIDE + kt * KT + 2 * c2];
            u32 hi, lo;
            cvt_split2(p2.x, p2.y, hi, lo);
            u32 off = SWZ_U32(r, c2);
            *(u32*)(smem + SM_QPHI + off) = hi;
            *(u32*)(smem + SM_QPLO + off) = lo;
        }
        __syncthreads();

        const int rowA = m0 + sub + ((grp & 1) << 3);
        const int rowB0 = sub + ((grp & 1) << 3);
        const int unitB = 2 * wn + (grp >> 1);
        #pragma unroll
        for (int ks = 0; ks < 8; ++ks) {
            int unitA = 2 * ks + (grp >> 1);
            u32 offA = SWZ_UNIT(rowA, unitA);
            u32 ah[4], al[4];
            ldm_x4(ah, sb + SM_QPHI + offA);
            ldm_x4(al, sb + SM_QPLO + offA);

            int rowB = ks * 16 + rowB0;
            u32 offB = SWZ_UNIT(rowB, unitB);
            u32 bh[4], bl[4];
            ldm_x4t(bh, sb + SM_KHI + offB);   // r0,r1 = d-tile n0; r2,r3 = n0+8
            ldm_x4t(bl, sb + SM_KLO + offB);

            #pragma unroll
            for (int tile = 0; tile < 2; ++tile) {
                mma16816(racc[tile], ah, bh + 2 * tile);
                mma16816(racc[tile], ah, bl + 2 * tile);
                mma16816(racc[tile], al, bh + 2 * tile);
            }
        }
    }

    // ---- result epilogue ----
    #pragma unroll
    for (int tile = 0; tile < 2; ++tile) {
        int col = n0 + tile * 8 + 2 * t;
        int row = q0 + m0 + g;
        *(float2*)&out_res[((size_t)b * TT + row) * DD + col] =
            make_float2(racc[tile][0], racc[tile][1]);
        *(float2*)&out_res[((size_t)b * TT + row + 8) * DD + col] =
            make_float2(racc[tile][2], racc[tile][3]);
    }
}

extern "C" void kernel_launch(void* const* d_in, const int* in_sizes, int n_in,
                              void* d_out, int out_size) {
    const float* key   = (const float*)d_in[0];
    const float* value = (const float*)d_in[1];
    const float* query = (const float*)d_in[2];
    const void*  mask  = d_in[3];
    const float* qmask = (const float*)d_in[4];

    float* out      = (float*)d_out;
    float* out_res  = out;                          // [B, T, D] first (tuple order)
    float* out_attn = out + (size_t)BB * TT * DD;   // [B, T, T] second

    probe_mask_kernel<<<1, 32>>>((const unsigned char*)mask);

    cudaFuncSetAttribute(mh_attn_mma2_kernel,
                         cudaFuncAttributeMaxDynamicSharedMemorySize, SM_TOTAL);

    dim3 grid(BB * (TT / QT));   // 2048 CTAs
    mh_attn_mma2_kernel<<<grid, NTHREADS, SM_TOTAL>>>(
        key, value, query, mask, qmask, out_res, out_attn);
}

// round 6
// speedup vs baseline: 3.1178x; 1.6693x over previous
#include <cuda_runtime.h>
#include <cuda_bf16.h>

typedef unsigned int u32;

#define BB 64
#define TT 1024
#define DD 128
#define QT 32                  // q rows per CTA
#define KT 64                  // k-seq tile
#define NTHREADS 512
#define SSTRIDE 1032
#define MASK_FILL_F (-4294967295.0f)
#define SCALE 0.08838834764831845f

// ---- smem layout (bytes) ----
#define SM_SS    0                          // 32 x 1032 f32 scores (132096)
#define SM_KV    132096                     // 2 stages x {hi 16KB, lo 16KB}
#define SM_QP    (SM_KV + 2*32768)          // phase1: Q image hi/lo (8KB+8KB)
                                            // phase3: 2 P stages x {hi 4KB, lo 4KB}
#define SM_TOTAL (SM_QP + 16384)            // 214016

// 256B-row tiles: 16B unit `unit` of row `row`
#define SWZ_UNIT(row, unit) ((u32)(row) * 256u + (((u32)(unit) ^ ((u32)(row) & 7u)) << 4))
// 128B-row tiles (P): 8 units per row
#define SWZP_UNIT(row, unit) ((u32)(row) * 128u + (((u32)(unit) ^ ((u32)(row) & 7u)) << 4))

// ---- precomputed bf16 hi/lo operand images (swizzled smem-identical tiles) ----
__device__ __align__(16) unsigned char g_QHI[1 << 24];
__device__ __align__(16) unsigned char g_QLO[1 << 24];
__device__ __align__(16) unsigned char g_KHI[1 << 24];
__device__ __align__(16) unsigned char g_KLO[1 << 24];
__device__ __align__(16) unsigned char g_VHI[1 << 24];
__device__ __align__(16) unsigned char g_VLO[1 << 24];

// ================= PTX helpers =================
__device__ __forceinline__ u32 smem_u32(const void* p) {
    u32 a;
    asm("{ .reg .u64 t; cvta.to.shared.u64 t, %1; cvt.u32.u64 %0, t; }" : "=r"(a) : "l"(p));
    return a;
}
__device__ __forceinline__ void cp16(u32 dst, const void* src) {
    asm volatile("cp.async.cg.shared.global [%0], [%1], 16;" :: "r"(dst), "l"(src));
}
#define CP_COMMIT() asm volatile("cp.async.commit_group;" ::: "memory")
#define CP_WAIT_ALL() asm volatile("cp.async.wait_group 0;" ::: "memory")

__device__ __forceinline__ void ldm_x4(u32* r, u32 addr) {
    asm volatile("ldmatrix.sync.aligned.m8n8.x4.shared.b16 {%0,%1,%2,%3}, [%4];"
                 : "=r"(r[0]), "=r"(r[1]), "=r"(r[2]), "=r"(r[3]) : "r"(addr));
}
__device__ __forceinline__ void ldm_x2(u32* r, u32 addr) {
    asm volatile("ldmatrix.sync.aligned.m8n8.x2.shared.b16 {%0,%1}, [%2];"
                 : "=r"(r[0]), "=r"(r[1]) : "r"(addr));
}
__device__ __forceinline__ void ldm_x4t(u32* r, u32 addr) {
    asm volatile("ldmatrix.sync.aligned.m8n8.x4.trans.shared.b16 {%0,%1,%2,%3}, [%4];"
                 : "=r"(r[0]), "=r"(r[1]), "=r"(r[2]), "=r"(r[3]) : "r"(addr));
}
__device__ __forceinline__ void mma16816(float* c, const u32* a, const u32* b) {
    asm volatile(
        "mma.sync.aligned.m16n8k16.row.col.f32.bf16.bf16.f32 "
        "{%0,%1,%2,%3}, {%4,%5,%6,%7}, {%8,%9}, {%0,%1,%2,%3};"
        : "+f"(c[0]), "+f"(c[1]), "+f"(c[2]), "+f"(c[3])
        : "r"(a[0]), "r"(a[1]), "r"(a[2]), "r"(a[3]), "r"(b[0]), "r"(b[1]));
}
__device__ __forceinline__ void cvt_split2(float x0, float x1, u32& hi, u32& lo) {
    __nv_bfloat16 h0 = __float2bfloat16(x0);
    __nv_bfloat16 h1 = __float2bfloat16(x1);
    __nv_bfloat16 l0 = __float2bfloat16(x0 - __bfloat162float(h0));
    __nv_bfloat16 l1 = __float2bfloat16(x1 - __bfloat162float(h1));
    __nv_bfloat162 H(h0, h1), L(l0, l1);
    hi = *reinterpret_cast<u32*>(&H);
    lo = *reinterpret_cast<u32*>(&L);
}

// ---------------- mask dtype probe (u8 / i32 / f32) ----------------
__device__ int g_mask_mode;

__global__ void probe_mask_kernel(const unsigned char* __restrict__ mask)
{
    if (threadIdx.x != 0 || blockIdx.x != 0) return;
    const float* mf = (const float*)mask;
    bool all_f01 = true;
    for (int i = 0; i < 1024; ++i) {
        float f = mf[i];
        if (f != 0.0f && f != 1.0f) { all_f01 = false; break; }
    }
    if (all_f01) { g_mask_mode = 2; return; }
    int any_high = 0;
    for (int i = 0; i < 4096; i += 4)
        any_high |= (mask[i + 1] | mask[i + 2] | mask[i + 3]);
    g_mask_mode = any_high ? 0 : 1;
}

__device__ __forceinline__ bool mask_at(const void* __restrict__ m, size_t idx, int mode)
{
    if (mode == 0) return ((const unsigned char*)m)[idx] != 0;
    if (mode == 1) return ((const int*)m)[idx] != 0;
    return ((const float*)m)[idx] != 0.0f;
}

// ---------------- prep: f32 -> bf16 hi/lo swizzled tile images ----------------
__global__ __launch_bounds__(512)
void prep_kernel(const float* __restrict__ query,
                 const float* __restrict__ key,
                 const float* __restrict__ value)
{
    int idx = blockIdx.x * blockDim.x + threadIdx.x;   // 3 * 1048576 total
    int tensor = idx >> 20;
    int u = idx & 1048575;           // b(6) | seq(10) | unit(4)
    int unit = u & 15;
    int seq = (u >> 4) & 1023;
    int b = u >> 14;

    const float* src;
    unsigned char *dhi, *dlo;
    float scale = 1.0f;
    size_t img;
    int r;
    if (tensor == 0) {
        src = query; dhi = g_QHI; dlo = g_QLO; scale = SCALE;
        img = (size_t)(b * 32 + (seq >> 5)) << 13; r = seq & 31;
    } else if (tensor == 1) {
        src = key; dhi = g_KHI; dlo = g_KLO;
        img = (size_t)(b * 16 + (seq >> 6)) << 14; r = seq & 63;
    } else {
        src = value; dhi = g_VHI; dlo = g_VLO;
        img = (size_t)(b * 16 + (seq >> 6)) << 14; r = seq & 63;
    }
    const float4* s4 = (const float4*)(src + ((size_t)b * TT + seq) * DD + unit * 8);
    float4 x0 = s4[0], x1 = s4[1];
    uint4 H, L;
    cvt_split2(x0.x * scale, x0.y * scale, H.x, L.x);
    cvt_split2(x0.z * scale, x0.w * scale, H.y, L.y);
    cvt_split2(x1.x * scale, x1.y * scale, H.z, L.z);
    cvt_split2(x1.z * scale, x1.w * scale, H.w, L.w);
    u32 off = (u32)r * 256u + (((u32)(unit ^ (r & 7))) << 4);
    *(uint4*)(dhi + img + off) = H;
    *(uint4*)(dlo + img + off) = L;
}

// ---------------- tile copy helpers ----------------
__device__ __forceinline__ void copy_kv_tile(u32 dst, const unsigned char* ghi,
                                             const unsigned char* glo, size_t base, int tid)
{
    #pragma unroll
    for (int i = 0; i < 2; ++i) {
        int c = tid + i * 512;
        cp16(dst + c * 16, ghi + base + (size_t)c * 16);
        cp16(dst + 16384 + c * 16, glo + base + (size_t)c * 16);
    }
}

// ================= fused attention =================
__global__ __launch_bounds__(NTHREADS, 1)
void mh_attn_mma3_kernel(const void* __restrict__ mask,
                         const float* __restrict__ qmask,
                         float* __restrict__ out_res,
                         float* __restrict__ out_attn)
{
    extern __shared__ char smem[];
    float* sS = (float*)smem;
    const u32 sb = smem_u32(smem);

    const int b    = blockIdx.x >> 5;
    const int q0   = (blockIdx.x & 31) * QT;
    const int tid  = threadIdx.x;
    const int wid  = tid >> 5;
    const int lane = tid & 31;
    const int grp  = lane >> 3;
    const int sub  = lane & 7;
    const int g    = lane >> 2;
    const int t    = lane & 3;
    const int wm   = wid & 1;
    const int wn   = wid >> 1;      // 0..7
    const int m0   = wm * 16;

    // ---- preload Q image + K tile 0 ----
    {
        size_t qimg = (size_t)(b * 32 + (q0 >> 5)) << 13;
        cp16(sb + SM_QP + tid * 16, g_QHI + qimg + (size_t)tid * 16);
        cp16(sb + SM_QP + 8192 + tid * 16, g_QLO + qimg + (size_t)tid * 16);
        copy_kv_tile(sb + SM_KV, g_KHI, g_KLO, (size_t)(b * 16) << 14, tid);
        CP_COMMIT();
        CP_WAIT_ALL();
    }
    __syncthreads();

    // ---- cache Q fragments (m16 x k128, hi+lo) ----
    u32 qhi[8][4], qlo[8][4];
    {
        int rowA = m0 + sub + ((grp & 1) << 3);
        #pragma unroll
        for (int ks = 0; ks < 8; ++ks) {
            u32 off = SWZ_UNIT(rowA, 2 * ks + (grp >> 1));
            ldm_x4(qhi[ks], sb + SM_QP + off);
            ldm_x4(qlo[ks], sb + SM_QP + 8192 + off);
        }
    }

    // =========== Phase 1: S = (Q*scale) @ K^T -> sS ===========
    {
        const int rowB = wn * 8 + sub;
        for (int kt = 0; kt < TT / KT; ++kt) {
            if (kt < 15) {
                copy_kv_tile(sb + SM_KV + ((kt + 1) & 1) * 32768,
                             g_KHI, g_KLO, (size_t)(b * 16 + kt + 1) << 14, tid);
                CP_COMMIT();
            }
            const u32 stage = sb + SM_KV + (kt & 1) * 32768;
            float acc[4] = {0.f, 0.f, 0.f, 0.f};
            #pragma unroll
            for (int ks = 0; ks < 8; ++ks) {
                u32 off = SWZ_UNIT(rowB, 2 * ks + (grp & 1));
                u32 bh[2], bl[2];
                ldm_x2(bh, stage + off);
                ldm_x2(bl, stage + 16384 + off);
                mma16816(acc, qhi[ks], bh);
                mma16816(acc, qhi[ks], bl);
                mma16816(acc, qlo[ks], bh);
            }
            int col = kt * KT + wn * 8 + 2 * t;
            *(float2*)&sS[(m0 + g) * SSTRIDE + col]     = make_float2(acc[0], acc[1]);
            *(float2*)&sS[(m0 + g + 8) * SSTRIDE + col] = make_float2(acc[2], acc[3]);
            if (kt < 15) CP_WAIT_ALL();
            __syncthreads();
        }
    }

    // =========== Phase 2: mask + softmax + query_mask, stream attn ===========
    {
        const int mmode = g_mask_mode;
        float* attn_g = out_attn + ((size_t)b * TT + q0) * TT;
        for (int r = wid; r < QT; r += 16) {
            float* row = sS + r * SSTRIDE;
            const size_t mrow = (size_t)b * TT * TT + (size_t)(q0 + r) * TT;
            float mx = -3.402823466e38f;
            for (int i = lane; i < TT; i += 32) {
                float s = row[i];
                if (mask_at(mask, mrow + i, mmode)) s = MASK_FILL_F;
                row[i] = s;
                mx = fmaxf(mx, s);
            }
            #pragma unroll
            for (int o = 16; o; o >>= 1) mx = fmaxf(mx, __shfl_xor_sync(0xffffffffu, mx, o));
            float sum = 0.f;
            for (int i = lane; i < TT; i += 32) {
                float e = __expf(row[i] - mx);
                sum += e;
                row[i] = e;
            }
            #pragma unroll
            for (int o = 16; o; o >>= 1) sum += __shfl_xor_sync(0xffffffffu, sum, o);
            float inv = qmask[(size_t)b * TT + q0 + r] / sum;
            for (int i = lane; i < TT; i += 32) {
                float v = row[i] * inv;
                row[i] = v;
                attn_g[(size_t)r * TT + i] = v;
            }
        }
    }
    __syncthreads();

    // =========== Phase 3: result = P @ V ===========
    float racc[2][4] = {{0.f,0.f,0.f,0.f},{0.f,0.f,0.f,0.f}};
    {
        // P convert for tile kt -> stage buffer
        auto convert_P = [&](int kt) {
            char* ps = smem + SM_QP + (kt & 1) * 8192;
            #pragma unroll
            for (int i = 0; i < 2; ++i) {
                int j = tid + i * 512;
                int r = j >> 5, c2 = j & 31;
                float2 p2 = *(const float2*)&sS[r * SSTRIDE + kt * KT + 2 * c2];
                u32 hi, lo;
                cvt_split2(p2.x, p2.y, hi, lo);
                u32 off = SWZP_UNIT(r, c2 >> 2) + ((c2 & 3) << 2);
                *(u32*)(ps + off) = hi;
                *(u32*)(ps + 4096 + off) = lo;
            }
        };

        convert_P(0);
        copy_kv_tile(sb + SM_KV, g_VHI, g_VLO, (size_t)(b * 16) << 14, tid);
        CP_COMMIT();
        CP_WAIT_ALL();
        __syncthreads();

        const int rowA  = m0 + sub + ((grp & 1) << 3);
        const int rowB0 = sub + ((grp & 1) << 3);
        const int unitB = 2 * wn + (grp >> 1);

        for (int kt = 0; kt < TT / KT; ++kt) {
            if (kt < 15) {
                copy_kv_tile(sb + SM_KV + ((kt + 1) & 1) * 32768,
                             g_VHI, g_VLO, (size_t)(b * 16 + kt + 1) << 14, tid);
                CP_COMMIT();
            }
            const u32 stV = sb + SM_KV + (kt & 1) * 32768;
            const u32 stP = sb + SM_QP + (kt & 1) * 8192;
            #pragma unroll
            for (int ks = 0; ks < 4; ++ks) {
                u32 offA = SWZP_UNIT(rowA, 2 * ks + (grp >> 1));
                u32 ah[4], al[4];
                ldm_x4(ah, stP + offA);
                ldm_x4(al, stP + 4096 + offA);
                u32 offB = SWZ_UNIT(ks * 16 + rowB0, unitB);
                u32 bh[4], bl[4];
                ldm_x4t(bh, stV + offB);
                ldm_x4t(bl, stV + 16384 + offB);
                #pragma unroll
                for (int tile = 0; tile < 2; ++tile) {
                    mma16816(racc[tile], ah, bh + 2 * tile);
                    mma16816(racc[tile], ah, bl + 2 * tile);
                    mma16816(racc[tile], al, bh + 2 * tile);
                }
            }
            if (kt < 15) {
                convert_P(kt + 1);
                CP_WAIT_ALL();
                __syncthreads();
            }
        }
    }

    // ---- result epilogue ----
    #pragma unroll
    for (int tile = 0; tile < 2; ++tile) {
        int col = wn * 16 + tile * 8 + 2 * t;
        int row = q0 + m0 + g;
        *(float2*)&out_res[((size_t)b * TT + row) * DD + col] =
            make_float2(racc[tile][0], racc[tile][1]);
        *(float2*)&out_res[((size_t)b * TT + row + 8) * DD + col] =
            make_float2(racc[tile][2], racc[tile][3]);
    }
}

extern "C" void kernel_launch(void* const* d_in, const int* in_sizes, int n_in,
                              void* d_out, int out_size) {
    const float* key   = (const float*)d_in[0];
    const float* value = (const float*)d_in[1];
    const float* query = (const float*)d_in[2];
    const void*  mask  = d_in[3];
    const float* qmask = (const float*)d_in[4];

    float* out      = (float*)d_out;
    float* out_res  = out;                          // [B, T, D] first (tuple order)
    float* out_attn = out + (size_t)BB * TT * DD;   // [B, T, T] second

    probe_mask_kernel<<<1, 32>>>((const unsigned char*)mask);
    prep_kernel<<<6144, 512>>>(query, key, value);

    cudaFuncSetAttribute(mh_attn_mma3_kernel,
                         cudaFuncAttributeMaxDynamicSharedMemorySize, SM_TOTAL);
    dim3 grid(BB * (TT / QT));   // 2048 CTAs
    mh_attn_mma3_kernel<<<grid, NTHREADS, SM_TOTAL>>>(mask, qmask, out_res, out_attn);
}

// round 7
// speedup vs baseline: 3.3238x; 1.0660x over previous
#include <cuda_runtime.h>
#include <cuda_bf16.h>

typedef unsigned int u32;

#define BB 64
#define TT 1024
#define DD 128
#define QT 32                  // q rows per CTA
#define KT 64                  // k-seq tile
#define NTHREADS 512
#define SSTRIDE 1032
#define MASK_FILL_F (-4294967295.0f)
#define SCALE 0.08838834764831845f

// ---- smem layout (bytes) ----
#define SM_SS    0                          // 32 x 1032 f32 scores (132096)
#define SM_KV    132096                     // 2 stages x {hi 16KB, lo 16KB}
#define SM_QP    (SM_KV + 2*32768)          // phase1: Q image hi/lo (8KB+8KB)
                                            // phase3: 2 P stages x {hi 4KB, lo 4KB}
#define SM_TOTAL (SM_QP + 16384)            // 214016

// 256B-row tiles: 16B unit `unit` of row `row`
#define SWZ_UNIT(row, unit) ((u32)(row) * 256u + (((u32)(unit) ^ ((u32)(row) & 7u)) << 4))
// 128B-row tiles (P): 8 units per row
#define SWZP_UNIT(row, unit) ((u32)(row) * 128u + (((u32)(unit) ^ ((u32)(row) & 7u)) << 4))

// ---- precomputed bf16 hi/lo operand images (swizzled smem-identical tiles) ----
__device__ __align__(16) unsigned char g_QHI[1 << 24];
__device__ __align__(16) unsigned char g_QLO[1 << 24];
__device__ __align__(16) unsigned char g_KHI[1 << 24];
__device__ __align__(16) unsigned char g_KLO[1 << 24];
__device__ __align__(16) unsigned char g_VHI[1 << 24];
__device__ __align__(16) unsigned char g_VLO[1 << 24];

// ================= PTX helpers =================
__device__ __forceinline__ u32 smem_u32(const void* p) {
    u32 a;
    asm("{ .reg .u64 t; cvta.to.shared.u64 t, %1; cvt.u32.u64 %0, t; }" : "=r"(a) : "l"(p));
    return a;
}
__device__ __forceinline__ void cp16(u32 dst, const void* src) {
    asm volatile("cp.async.cg.shared.global [%0], [%1], 16;" :: "r"(dst), "l"(src));
}
#define CP_COMMIT() asm volatile("cp.async.commit_group;" ::: "memory")
#define CP_WAIT_ALL() asm volatile("cp.async.wait_group 0;" ::: "memory")

__device__ __forceinline__ void ldm_x4(u32* r, u32 addr) {
    asm volatile("ldmatrix.sync.aligned.m8n8.x4.shared.b16 {%0,%1,%2,%3}, [%4];"
                 : "=r"(r[0]), "=r"(r[1]), "=r"(r[2]), "=r"(r[3]) : "r"(addr));
}
__device__ __forceinline__ void ldm_x4t(u32* r, u32 addr) {
    asm volatile("ldmatrix.sync.aligned.m8n8.x4.trans.shared.b16 {%0,%1,%2,%3}, [%4];"
                 : "=r"(r[0]), "=r"(r[1]), "=r"(r[2]), "=r"(r[3]) : "r"(addr));
}
__device__ __forceinline__ void mma16816(float* c, const u32* a, const u32* b) {
    asm volatile(
        "mma.sync.aligned.m16n8k16.row.col.f32.bf16.bf16.f32 "
        "{%0,%1,%2,%3}, {%4,%5,%6,%7}, {%8,%9}, {%0,%1,%2,%3};"
        : "+f"(c[0]), "+f"(c[1]), "+f"(c[2]), "+f"(c[3])
        : "r"(a[0]), "r"(a[1]), "r"(a[2]), "r"(a[3]), "r"(b[0]), "r"(b[1]));
}
__device__ __forceinline__ void cvt_split2(float x0, float x1, u32& hi, u32& lo) {
    __nv_bfloat16 h0 = __float2bfloat16(x0);
    __nv_bfloat16 h1 = __float2bfloat16(x1);
    __nv_bfloat16 l0 = __float2bfloat16(x0 - __bfloat162float(h0));
    __nv_bfloat16 l1 = __float2bfloat16(x1 - __bfloat162float(h1));
    __nv_bfloat162 H(h0, h1), L(l0, l1);
    hi = *reinterpret_cast<u32*>(&H);
    lo = *reinterpret_cast<u32*>(&L);
}

// ---------------- mask dtype probe (u8 / i32 / f32), warp-parallel ----------------
__device__ int g_mask_mode;

__global__ void probe_mask_kernel(const unsigned char* __restrict__ mask)
{
    const int lane = threadIdx.x;
    const float* mf = (const float*)mask;
    bool f01 = true;
    for (int i = lane; i < 1024; i += 32) {
        float f = mf[i];
        if (f != 0.0f && f != 1.0f) f01 = false;
    }
    if (__all_sync(0xffffffffu, f01)) {
        if (lane == 0) g_mask_mode = 2;
        return;
    }
    u32 any_high = 0;
    for (int i = lane * 4; i < 4096; i += 128)
        any_high |= (mask[i + 1] | mask[i + 2] | mask[i + 3]);
    int any = __any_sync(0xffffffffu, any_high != 0);
    if (lane == 0) g_mask_mode = any ? 0 : 1;
}

__device__ __forceinline__ bool mask_at(const void* __restrict__ m, size_t idx, int mode)
{
    if (mode == 0) return ((const unsigned char*)m)[idx] != 0;
    if (mode == 1) return ((const int*)m)[idx] != 0;
    return ((const float*)m)[idx] != 0.0f;
}

// ---------------- prep: f32 -> bf16 hi/lo swizzled tile images ----------------
__global__ __launch_bounds__(512)
void prep_kernel(const float* __restrict__ query,
                 const float* __restrict__ key,
                 const float* __restrict__ value)
{
    int idx = blockIdx.x * blockDim.x + threadIdx.x;   // 3 * 1048576 total
    int tensor = idx >> 20;
    int u = idx & 1048575;           // b(6) | seq(10) | unit(4)
    int unit = u & 15;
    int seq = (u >> 4) & 1023;
    int b = u >> 14;

    const float* src;
    unsigned char *dhi, *dlo;
    float scale = 1.0f;
    size_t img;
    int r;
    if (tensor == 0) {
        src = query; dhi = g_QHI; dlo = g_QLO; scale = SCALE;
        img = (size_t)(b * 32 + (seq >> 5)) << 13; r = seq & 31;
    } else if (tensor == 1) {
        src = key; dhi = g_KHI; dlo = g_KLO;
        img = (size_t)(b * 16 + (seq >> 6)) << 14; r = seq & 63;
    } else {
        src = value; dhi = g_VHI; dlo = g_VLO;
        img = (size_t)(b * 16 + (seq >> 6)) << 14; r = seq & 63;
    }
    const float4* s4 = (const float4*)(src + ((size_t)b * TT + seq) * DD + unit * 8);
    float4 x0 = s4[0], x1 = s4[1];
    uint4 H, L;
    cvt_split2(x0.x * scale, x0.y * scale, H.x, L.x);
    cvt_split2(x0.z * scale, x0.w * scale, H.y, L.y);
    cvt_split2(x1.x * scale, x1.y * scale, H.z, L.z);
    cvt_split2(x1.z * scale, x1.w * scale, H.w, L.w);
    u32 off = (u32)r * 256u + (((u32)(unit ^ (r & 7))) << 4);
    *(uint4*)(dhi + img + off) = H;
    *(uint4*)(dlo + img + off) = L;
}

// ---------------- tile copy helpers ----------------
__device__ __forceinline__ void copy_kv_tile(u32 dst, const unsigned char* ghi,
                                             const unsigned char* glo, size_t base, int tid)
{
    #pragma unroll
    for (int i = 0; i < 2; ++i) {
        int c = tid + i * 512;
        cp16(dst + c * 16, ghi + base + (size_t)c * 16);
        cp16(dst + 16384 + c * 16, glo + base + (size_t)c * 16);
    }
}

// ================= fused attention =================
__global__ __launch_bounds__(NTHREADS, 1)
void mh_attn_mma4_kernel(const void* __restrict__ mask,
                         const float* __restrict__ qmask,
                         float* __restrict__ out_res,
                         float* __restrict__ out_attn)
{
    extern __shared__ char smem[];
    float* sS = (float*)smem;
    const u32 sb = smem_u32(smem);

    const int b    = blockIdx.x >> 5;
    const int q0   = (blockIdx.x & 31) * QT;
    const int tid  = threadIdx.x;
    const int wid  = tid >> 5;
    const int lane = tid & 31;
    const int grp  = lane >> 3;
    const int sub  = lane & 7;
    const int g    = lane >> 2;
    const int t    = lane & 3;
    const int wm   = wid & 1;
    const int wn   = wid >> 1;      // 0..7
    const int m0   = wm * 16;

    // ---- preload Q image + K tile 0 ----
    {
        size_t qimg = (size_t)(b * 32 + (q0 >> 5)) << 13;
        cp16(sb + SM_QP + tid * 16, g_QHI + qimg + (size_t)tid * 16);
        cp16(sb + SM_QP + 8192 + tid * 16, g_QLO + qimg + (size_t)tid * 16);
        copy_kv_tile(sb + SM_KV, g_KHI, g_KLO, (size_t)(b * 16) << 14, tid);
        CP_COMMIT();
        CP_WAIT_ALL();
    }
    __syncthreads();

    // ---- cache Q fragments (m16 x k128, hi+lo) ----
    u32 qhi[8][4], qlo[8][4];
    {
        int rowA = m0 + sub + ((grp & 1) << 3);
        #pragma unroll
        for (int ks = 0; ks < 8; ++ks) {
            u32 off = SWZ_UNIT(rowA, 2 * ks + (grp >> 1));
            ldm_x4(qhi[ks], sb + SM_QP + off);
            ldm_x4(qlo[ks], sb + SM_QP + 8192 + off);
        }
    }

    // =========== Phase 1: S = (Q*scale) @ K^T -> sS ===========
    {
        // mixed-address ldmatrix: lanes 0-15 read hi tile, lanes 16-31 lo tile
        const int rowB   = wn * 8 + sub;
        const u32 hilo   = (grp >> 1) ? 16384u : 0u;
        for (int kt = 0; kt < TT / KT; ++kt) {
            if (kt < 15) {
                copy_kv_tile(sb + SM_KV + ((kt + 1) & 1) * 32768,
                             g_KHI, g_KLO, (size_t)(b * 16 + kt + 1) << 14, tid);
                CP_COMMIT();
            }
            const u32 stage = sb + SM_KV + (kt & 1) * 32768 + hilo;
            float ahh[4] = {0.f,0.f,0.f,0.f};
            float ahl[4] = {0.f,0.f,0.f,0.f};
            float alh[4] = {0.f,0.f,0.f,0.f};
            #pragma unroll
            for (int ks = 0; ks < 8; ++ks) {
                u32 bb[4];   // bb[0..1]=bhi, bb[2..3]=blo
                ldm_x4(bb, stage + SWZ_UNIT(rowB, 2 * ks + (grp & 1)));
                mma16816(ahh, qhi[ks], bb);
                mma16816(ahl, qhi[ks], bb + 2);
                mma16816(alh, qlo[ks], bb);
            }
            int col = kt * KT + wn * 8 + 2 * t;
            *(float2*)&sS[(m0 + g) * SSTRIDE + col] =
                make_float2(ahh[0] + ahl[0] + alh[0], ahh[1] + ahl[1] + alh[1]);
            *(float2*)&sS[(m0 + g + 8) * SSTRIDE + col] =
                make_float2(ahh[2] + ahl[2] + alh[2], ahh[3] + ahl[3] + alh[3]);
            if (kt < 15) CP_WAIT_ALL();
            __syncthreads();
        }
    }

    // =========== Phase 2: mask + softmax + query_mask, stream attn ===========
    {
        const int mmode = g_mask_mode;
        float* attn_g = out_attn + ((size_t)b * TT + q0) * TT;
        for (int r = wid; r < QT; r += 16) {
            float* row = sS + r * SSTRIDE;
            const size_t mrow = (size_t)b * TT * TT + (size_t)(q0 + r) * TT;
            float mx = -3.402823466e38f;
            for (int i = lane; i < TT; i += 32) {
                float s = row[i];
                if (mask_at(mask, mrow + i, mmode)) s = MASK_FILL_F;
                row[i] = s;
                mx = fmaxf(mx, s);
            }
            #pragma unroll
            for (int o = 16; o; o >>= 1) mx = fmaxf(mx, __shfl_xor_sync(0xffffffffu, mx, o));
            float sum = 0.f;
            for (int i = lane; i < TT; i += 32) {
                float e = __expf(row[i] - mx);
                sum += e;
                row[i] = e;
            }
            #pragma unroll
            for (int o = 16; o; o >>= 1) sum += __shfl_xor_sync(0xffffffffu, sum, o);
            float inv = qmask[(size_t)b * TT + q0 + r] / sum;
            for (int i = lane; i < TT; i += 32) {
                float v = row[i] * inv;
                row[i] = v;
                attn_g[(size_t)r * TT + i] = v;
            }
        }
    }
    __syncthreads();

    // =========== Phase 3: result = P @ V ===========
    float rhh[2][4] = {{0.f,0.f,0.f,0.f},{0.f,0.f,0.f,0.f}};
    float rhl[2][4] = {{0.f,0.f,0.f,0.f},{0.f,0.f,0.f,0.f}};
    float rlh[2][4] = {{0.f,0.f,0.f,0.f},{0.f,0.f,0.f,0.f}};
    {
        auto convert_P = [&](int kt) {
            char* ps = smem + SM_QP + (kt & 1) * 8192;
            #pragma unroll
            for (int i = 0; i < 2; ++i) {
                int j = tid + i * 512;
                int r = j >> 5, c2 = j & 31;
                float2 p2 = *(const float2*)&sS[r * SSTRIDE + kt * KT + 2 * c2];
                u32 hi, lo;
                cvt_split2(p2.x, p2.y, hi, lo);
                u32 off = SWZP_UNIT(r, c2 >> 2) + ((c2 & 3) << 2);
                *(u32*)(ps + off) = hi;
                *(u32*)(ps + 4096 + off) = lo;
            }
        };

        convert_P(0);
        copy_kv_tile(sb + SM_KV, g_VHI, g_VLO, (size_t)(b * 16) << 14, tid);
        CP_COMMIT();
        CP_WAIT_ALL();
        __syncthreads();

        const int rowA  = m0 + sub + ((grp & 1) << 3);
        const int rowB0 = sub + ((grp & 1) << 3);
        const int unitB = 2 * wn + (grp >> 1);

        for (int kt = 0; kt < TT / KT; ++kt) {
            if (kt < 15) {
                copy_kv_tile(sb + SM_KV + ((kt + 1) & 1) * 32768,
                             g_VHI, g_VLO, (size_t)(b * 16 + kt + 1) << 14, tid);
                CP_COMMIT();
            }
            const u32 stV = sb + SM_KV + (kt & 1) * 32768;
            const u32 stP = sb + SM_QP + (kt & 1) * 8192;
            #pragma unroll
            for (int ks = 0; ks < 4; ++ks) {
                u32 offA = SWZP_UNIT(rowA, 2 * ks + (grp >> 1));
                u32 ah[4], al[4];
                ldm_x4(ah, stP + offA);
                ldm_x4(al, stP + 4096 + offA);
                u32 offB = SWZ_UNIT(ks * 16 + rowB0, unitB);
                u32 bh[4], bl[4];
                ldm_x4t(bh, stV + offB);
                ldm_x4t(bl, stV + 16384 + offB);
                #pragma unroll
                for (int tile = 0; tile < 2; ++tile) {
                    mma16816(rhh[tile], ah, bh + 2 * tile);
                    mma16816(rhl[tile], ah, bl + 2 * tile);
                    mma16816(rlh[tile], al, bh + 2 * tile);
                }
            }
            if (kt < 15) {
                convert_P(kt + 1);
                CP_WAIT_ALL();
                __syncthreads();
            }
        }
    }

    // ---- result epilogue ----
    #pragma unroll
    for (int tile = 0; tile < 2; ++tile) {
        int col = wn * 16 + tile * 8 + 2 * t;
        int row = q0 + m0 + g;
        *(float2*)&out_res[((size_t)b * TT + row) * DD + col] =
            make_float2(rhh[tile][0] + rhl[tile][0] + rlh[tile][0],
                        rhh[tile][1] + rhl[tile][1] + rlh[tile][1]);
        *(float2*)&out_res[((size_t)b * TT + row + 8) * DD + col] =
            make_float2(rhh[tile][2] + rhl[tile][2] + rlh[tile][2],
                        rhh[tile][3] + rhl[tile][3] + rlh[tile][3]);
    }
}

extern "C" void kernel_launch(void* const* d_in, const int* in_sizes, int n_in,
                              void* d_out, int out_size) {
    const float* key   = (const float*)d_in[0];
    const float* value = (const float*)d_in[1];
    const float* query = (const float*)d_in[2];
    const void*  mask  = d_in[3];
    const float* qmask = (const float*)d_in[4];

    float* out      = (float*)d_out;
    float* out_res  = out;                          // [B, T, D] first (tuple order)
    float* out_attn = out + (size_t)BB * TT * DD;   // [B, T, T] second

    probe_mask_kernel<<<1, 32>>>((const unsigned char*)mask);
    prep_kernel<<<6144, 512>>>(query, key, value);

    cudaFuncSetAttribute(mh_attn_mma4_kernel,
                         cudaFuncAttributeMaxDynamicSharedMemorySize, SM_TOTAL);
    dim3 grid(BB * (TT / QT));   // 2048 CTAs
    mh_attn_mma4_kernel<<<grid, NTHREADS, SM_TOTAL>>>(mask, qmask, out_res, out_attn);
}